// round 3
// baseline (speedup 1.0000x reference)
#include <cuda_runtime.h>
#include <cstdint>

// ============================================================================
// Problem constants
// ============================================================================
#define BS_ROWS   16384          // B*S
#define HDIM      1024
#define NELT      16777216       // BS_ROWS * HDIM
#define QSCALE    ((float)(2.5/127.0))
#define QINV      ((float)(127.0/2.5))

// ============================================================================
// Device scratch (static — no runtime allocation)
// ============================================================================
static __device__ __align__(16) int8_t g_qx[2][(size_t)NELT];      // quantized activations
static __device__ __align__(16) int8_t g_qw[2][(size_t)HDIM*HDIM]; // quantized weights
static __device__ float  g_y[2][(size_t)NELT];                     // dropout(scale2*acc+bias)
static __device__ uint4  g_subkeys;

// ============================================================================
// Helpers
// ============================================================================
__device__ __forceinline__ uint32_t smem_u32(const void* p) {
    uint32_t a;
    asm("{ .reg .u64 t; cvta.to.shared.u64 t, %1; cvt.u32.u64 %0, t; }" : "=r"(a) : "l"(p));
    return a;
}

#define SWZ128(off) ((off) ^ (((off) >> 3) & 0x70u))

__device__ __forceinline__ void cp_async16(uint32_t dst, const void* src) {
    asm volatile("cp.async.cg.shared.global [%0], [%1], 16;" :: "r"(dst), "l"(src));
}
#define CP_COMMIT() asm volatile("cp.async.commit_group;" ::: "memory")
#define CP_WAIT(n)  asm volatile("cp.async.wait_group %0;" :: "n"(n) : "memory")

__device__ __forceinline__ void ldsm4(uint32_t* r, uint32_t addr) {
    asm volatile("ldmatrix.sync.aligned.m8n8.x4.shared.b16 {%0,%1,%2,%3}, [%4];"
                 : "=r"(r[0]), "=r"(r[1]), "=r"(r[2]), "=r"(r[3]) : "r"(addr));
}

__device__ __forceinline__ void imma16832(int* d, const uint32_t* a, uint32_t b0, uint32_t b1) {
    asm volatile("mma.sync.aligned.m16n8k32.row.col.s32.s8.s8.s32 "
                 "{%0,%1,%2,%3}, {%4,%5,%6,%7}, {%8,%9}, {%0,%1,%2,%3};"
                 : "+r"(d[0]), "+r"(d[1]), "+r"(d[2]), "+r"(d[3])
                 : "r"(a[0]), "r"(a[1]), "r"(a[2]), "r"(a[3]), "r"(b0), "r"(b1));
}

// ============================================================================
// JAX threefry2x32 (partitionable bits path: counter (0,i), xor-fold)
// ============================================================================
__device__ __forceinline__ uint2 threefry2x32_pair(uint32_t k0, uint32_t k1,
                                                   uint32_t x0, uint32_t x1) {
    uint32_t ks2 = k0 ^ k1 ^ 0x1BD11BDAu;
    x0 += k0; x1 += k1;
#define TF_R(r) { x0 += x1; x1 = (x1 << (r)) | (x1 >> (32 - (r))); x1 ^= x0; }
    TF_R(13) TF_R(15) TF_R(26) TF_R(6)
    x0 += k1;  x1 += ks2 + 1u;
    TF_R(17) TF_R(29) TF_R(16) TF_R(24)
    x0 += ks2; x1 += k0 + 2u;
    TF_R(13) TF_R(15) TF_R(26) TF_R(6)
    x0 += k0;  x1 += k1 + 3u;
    TF_R(17) TF_R(29) TF_R(16) TF_R(24)
    x0 += k1;  x1 += ks2 + 4u;
    TF_R(13) TF_R(15) TF_R(26) TF_R(6)
    x0 += ks2; x1 += k0 + 5u;
#undef TF_R
    return make_uint2(x0, x1);
}

__device__ __forceinline__ uint32_t threefry_fold(uint32_t k0, uint32_t k1, uint32_t idx) {
    uint2 o = threefry2x32_pair(k0, k1, 0u, idx);
    return o.x ^ o.y;
}

// subkeys = foldlike split of key(42): subkey_i = threefry(key, (0, i)) (both words)
__global__ void subkey_kernel() {
    if (threadIdx.x == 0) {
        uint2 a = threefry2x32_pair(0u, 42u, 0u, 0u);
        uint2 b = threefry2x32_pair(0u, 42u, 0u, 1u);
        g_subkeys = make_uint4(a.x, a.y, b.x, b.y);
    }
}

// ============================================================================
// Quant: float -> int8 level (exact)
// ============================================================================
__global__ __launch_bounds__(256) void quant_kernel(const float* __restrict__ x,
                                                    int which, int n4) {
    int8_t* q = (which == 0) ? g_qx[0] : (which == 1) ? g_qx[1]
              : (which == 2) ? g_qw[0] : g_qw[1];
    int i = blockIdx.x * blockDim.x + threadIdx.x;
    if (i >= n4) return;
    float4 v = reinterpret_cast<const float4*>(x)[i];
    int a0 = __float2int_rn(fminf(fmaxf(v.x, -2.5f), 2.5f) * QINV);
    int a1 = __float2int_rn(fminf(fmaxf(v.y, -2.5f), 2.5f) * QINV);
    int a2 = __float2int_rn(fminf(fmaxf(v.z, -2.5f), 2.5f) * QINV);
    int a3 = __float2int_rn(fminf(fmaxf(v.w, -2.5f), 2.5f) * QINV);
    uint32_t pk = (uint32_t)(a0 & 0xff) | ((uint32_t)(a1 & 0xff) << 8)
                | ((uint32_t)(a2 & 0xff) << 16) | ((uint32_t)(a3 & 0xff) << 24);
    reinterpret_cast<uint32_t*>(q)[i] = pk;
}

// ============================================================================
// Int8 GEMM (mma.sync m16n8k32) + fused scale/bias/threefry-dropout epilogue
// CTA tile 128x128, K-chunk 128 (128B SW128 rows), 3-stage cp.async pipeline.
// Warps: 4(m) x 2(n); warp tile 32x64.
// ============================================================================
#define KCHUNKS 8          // 1024 / 128
#define STAGE_BYTES 32768  // A 16KB + B 16KB
#define NSTAGES 3

__device__ __forceinline__ void load_stage(const int8_t* __restrict__ X,
                                           const int8_t* __restrict__ Wt,
                                           int m0, int n0, uint32_t smem_base,
                                           int tid, int kc, int slot) {
    uint32_t sb = smem_base + (uint32_t)slot * STAGE_BYTES;
    const int kof = kc * 128;
#pragma unroll
    for (int i = 0; i < 4; i++) {
        int lin = tid + i * 256;
        int row = lin >> 3, seg = lin & 7;
        uint32_t off = SWZ128((uint32_t)(row * 128 + seg * 16));
        cp_async16(sb + off,          X  + (size_t)(m0 + row) * HDIM + kof + seg * 16);
        cp_async16(sb + 16384u + off, Wt + (size_t)(n0 + row) * HDIM + kof + seg * 16);
    }
    CP_COMMIT();
}

__global__ __launch_bounds__(256, 2) void gemm_kernel(const float* __restrict__ bias1,
                                                      const float* __restrict__ bias2) {
    extern __shared__ __align__(1024) char smem[];
    const uint32_t smem_base = smem_u32(smem);
    const int tid  = threadIdx.x;
    const int wid  = tid >> 5, lane = tid & 31;
    const int gemm = blockIdx.y;
    const int m0 = (blockIdx.x >> 3) * 128;
    const int n0 = (blockIdx.x & 7) * 128;
    const int wm = (wid & 3) * 32, wn = (wid >> 2) * 64;

    const int8_t* __restrict__ X  = g_qx[gemm];
    const int8_t* __restrict__ Wt = g_qw[gemm];
    const float*  __restrict__ bias = gemm ? bias2 : bias1;

    // precomputed swizzled ldmatrix base offsets (XOR ks*32 per k-step)
    uint32_t sA[2], sB[4];
#pragma unroll
    for (int mi = 0; mi < 2; mi++) {
        int row = wm + mi * 16 + ((lane >> 3) & 1) * 8 + (lane & 7);
        sA[mi] = SWZ128((uint32_t)(row * 128 + ((lane >> 4) << 4)));
    }
#pragma unroll
    for (int g = 0; g < 4; g++) {
        int col = wn + g * 16 + ((lane >> 4) << 3) + (lane & 7);
        sB[g] = SWZ128((uint32_t)(col * 128 + (((lane >> 3) & 1) << 4)));
    }

    int acc[2][8][4];
#pragma unroll
    for (int mi = 0; mi < 2; mi++)
#pragma unroll
        for (int nf = 0; nf < 8; nf++)
#pragma unroll
            for (int j = 0; j < 4; j++) acc[mi][nf][j] = 0;

    load_stage(X, Wt, m0, n0, smem_base, tid, 0, 0);
    load_stage(X, Wt, m0, n0, smem_base, tid, 1, 1);

#pragma unroll 1
    for (int kc = 0; kc < KCHUNKS; kc++) {
        if (kc < KCHUNKS - 2) { CP_WAIT(1); } else { CP_WAIT(0); }
        __syncthreads();
        if (kc + 2 < KCHUNKS)
            load_stage(X, Wt, m0, n0, smem_base, tid, kc + 2, (kc + 2) % NSTAGES);

        const uint32_t aBase = smem_base + (uint32_t)(kc % NSTAGES) * STAGE_BYTES;
        const uint32_t bBase = aBase + 16384u;
#pragma unroll
        for (int ks = 0; ks < 4; ks++) {
            uint32_t a[2][4], b[4][4];
            const uint32_t kx = (uint32_t)(ks << 5);
            ldsm4(a[0], aBase + (sA[0] ^ kx));
            ldsm4(a[1], aBase + (sA[1] ^ kx));
#pragma unroll
            for (int g = 0; g < 4; g++) ldsm4(b[g], bBase + (sB[g] ^ kx));
#pragma unroll
            for (int mi = 0; mi < 2; mi++)
#pragma unroll
                for (int nf = 0; nf < 8; nf++)
                    imma16832(acc[mi][nf], a[mi],
                              b[nf >> 1][(nf & 1) * 2], b[nf >> 1][(nf & 1) * 2 + 1]);
        }
        __syncthreads();
    }

    // ---- fused epilogue: scale2*acc + bias, threefry dropout, store f32 ----
    const float scale2 = QSCALE * QSCALE;
    const float inv_keep = 1.0f / 0.9f;
    const uint4 sk = g_subkeys;
    const uint32_t k0 = gemm ? sk.z : sk.x;
    const uint32_t k1 = gemm ? sk.w : sk.y;
    float* __restrict__ Y = g_y[gemm];

#pragma unroll
    for (int nf = 0; nf < 8; nf++) {
        const int c = n0 + wn + nf * 8 + 2 * (lane & 3);
        const float2 bv = *reinterpret_cast<const float2*>(bias + c);
#pragma unroll
        for (int mi = 0; mi < 2; mi++) {
#pragma unroll
            for (int h = 0; h < 2; h++) {
                const int r = m0 + wm + mi * 16 + (lane >> 2) + h * 8;
                float v0 = (float)acc[mi][nf][h * 2 + 0] * scale2 + bv.x;
                float v1 = (float)acc[mi][nf][h * 2 + 1] * scale2 + bv.y;
                const uint32_t idx = (uint32_t)r * HDIM + (uint32_t)c;
                uint32_t r0 = threefry_fold(k0, k1, idx);
                uint32_t r1 = threefry_fold(k0, k1, idx + 1u);
                v0 = ((r0 >> 9) < 7549747u) ? v0 * inv_keep : 0.0f;
                v1 = ((r1 >> 9) < 7549747u) ? v1 * inv_keep : 0.0f;
                *reinterpret_cast<float2*>(Y + (size_t)r * HDIM + c) = make_float2(v0, v1);
            }
        }
    }
}

// ============================================================================
// Residual + 2x LayerNorm
// ============================================================================
__device__ __forceinline__ float blk_sum(float v, float* sbuf) {
    const int lane = threadIdx.x & 31, w = threadIdx.x >> 5;
#pragma unroll
    for (int o = 16; o; o >>= 1) v += __shfl_xor_sync(0xffffffffu, v, o);
    __syncthreads();
    if (lane == 0) sbuf[w] = v;
    __syncthreads();
    float t = 0.f;
#pragma unroll
    for (int i = 0; i < 8; i++) t += sbuf[i];
    return t;
}

__global__ __launch_bounds__(256) void epi_kernel(
    const float* __restrict__ inp,
    const float* __restrict__ g1, const float* __restrict__ be1,
    const float* __restrict__ g2, const float* __restrict__ be2,
    float* __restrict__ out)
{
    __shared__ float sbuf[8];
    const int row = blockIdx.x;
    const int tid = threadIdx.x;
    const size_t base = (size_t)row * HDIM;
    const int o = tid * 4;

    const float4 xin = *reinterpret_cast<const float4*>(inp + base + o);

#pragma unroll 1
    for (int p = 0; p < 2; p++) {
        const float* __restrict__ gg = p ? g2  : g1;
        const float* __restrict__ ee = p ? be2 : be1;
        const float4 y = *reinterpret_cast<const float4*>(g_y[p] + base + o);
        float v0 = y.x + xin.x, v1 = y.y + xin.y, v2 = y.z + xin.z, v3 = y.w + xin.w;

        float s  = blk_sum(v0 + v1 + v2 + v3, sbuf);
        float mu = s * (1.0f / 1024.0f);
        float d0 = v0 - mu, d1 = v1 - mu, d2 = v2 - mu, d3 = v3 - mu;
        float sq  = blk_sum(d0 * d0 + d1 * d1 + d2 * d2 + d3 * d3, sbuf);
        float rs  = rsqrtf(sq * (1.0f / 1024.0f) + 1e-12f);

        const float4 gv = *reinterpret_cast<const float4*>(gg + o);
        const float4 ev = *reinterpret_cast<const float4*>(ee + o);
        float4 ov = make_float4(d0 * rs * gv.x + ev.x, d1 * rs * gv.y + ev.y,
                                d2 * rs * gv.z + ev.z, d3 * rs * gv.w + ev.w);
        *reinterpret_cast<float4*>(out + (size_t)p * NELT + base + o) = ov;
    }
}

// ============================================================================
// Launch
// ============================================================================
extern "C" void kernel_launch(void* const* d_in, const int* in_sizes, int n_in,
                              void* d_out, int out_size) {
    const float* hs1 = (const float*)d_in[0];
    const float* hs2 = (const float*)d_in[1];
    const float* inp = (const float*)d_in[2];
    const float* W1  = (const float*)d_in[3];
    const float* b1  = (const float*)d_in[4];
    const float* W2  = (const float*)d_in[5];
    const float* b2  = (const float*)d_in[6];
    const float* g1  = (const float*)d_in[7];
    const float* be1 = (const float*)d_in[8];
    const float* g2  = (const float*)d_in[9];
    const float* be2 = (const float*)d_in[10];
    float* out = (float*)d_out;

    const int n4x = NELT / 4;
    const int n4w = (HDIM * HDIM) / 4;

    subkey_kernel<<<1, 32>>>();
    quant_kernel<<<(n4x + 255) / 256, 256>>>(hs1, 0, n4x);
    quant_kernel<<<(n4x + 255) / 256, 256>>>(hs2, 1, n4x);
    quant_kernel<<<(n4w + 255) / 256, 256>>>(W1, 2, n4w);
    quant_kernel<<<(n4w + 255) / 256, 256>>>(W2, 3, n4w);

    static int smem_set = 0;
    if (!smem_set) {
        cudaFuncSetAttribute(gemm_kernel, cudaFuncAttributeMaxDynamicSharedMemorySize,
                             NSTAGES * STAGE_BYTES);
        smem_set = 1;
    }
    gemm_kernel<<<dim3(1024, 2), 256, NSTAGES * STAGE_BYTES>>>(b1, b2);

    epi_kernel<<<BS_ROWS, 256>>>(inp, g1, be1, g2, be2, out);
}

// round 6
// speedup vs baseline: 1.1012x; 1.1012x over previous
#include <cuda_runtime.h>
#include <cstdint>

// ============================================================================
// Problem constants
// ============================================================================
#define BS_ROWS   16384          // B*S
#define HDIM      1024
#define NELT      16777216       // BS_ROWS * HDIM
#define QSCALE    ((float)(2.5/127.0))
#define QINV      ((float)(127.0/2.5))
#define KEEP_THR  7549747u       // m < 0.9f*2^23  (exact)

// ============================================================================
// Device scratch (static — no runtime allocation)
// ============================================================================
static __device__ __align__(16) int8_t  g_qx[2][(size_t)NELT];      // quantized activations
static __device__ __align__(16) int8_t  g_qw[2][(size_t)HDIM*HDIM]; // quantized weights
static __device__ float   g_y[2][(size_t)NELT];                     // gemm outputs
static __device__ __align__(16) uint8_t g_mask[(size_t)NELT / 8];   // gemm1 dropout bitmask
static __device__ uint4   g_subkeys;

// ============================================================================
// Helpers
// ============================================================================
__device__ __forceinline__ uint32_t smem_u32(const void* p) {
    uint32_t a;
    asm("{ .reg .u64 t; cvta.to.shared.u64 t, %1; cvt.u32.u64 %0, t; }" : "=r"(a) : "l"(p));
    return a;
}

#define SWZ128(off) ((off) ^ (((off) >> 3) & 0x70u))

__device__ __forceinline__ void cp_async16(uint32_t dst, const void* src) {
    asm volatile("cp.async.cg.shared.global [%0], [%1], 16;" :: "r"(dst), "l"(src));
}
#define CP_COMMIT() asm volatile("cp.async.commit_group;" ::: "memory")
#define CP_WAIT(n)  asm volatile("cp.async.wait_group %0;" :: "n"(n) : "memory")

__device__ __forceinline__ void ldsm4(uint32_t* r, uint32_t addr) {
    asm volatile("ldmatrix.sync.aligned.m8n8.x4.shared.b16 {%0,%1,%2,%3}, [%4];"
                 : "=r"(r[0]), "=r"(r[1]), "=r"(r[2]), "=r"(r[3]) : "r"(addr));
}

__device__ __forceinline__ void imma16832(int* d, const uint32_t* a, uint32_t b0, uint32_t b1) {
    asm volatile("mma.sync.aligned.m16n8k32.row.col.s32.s8.s8.s32 "
                 "{%0,%1,%2,%3}, {%4,%5,%6,%7}, {%8,%9}, {%0,%1,%2,%3};"
                 : "+r"(d[0]), "+r"(d[1]), "+r"(d[2]), "+r"(d[3])
                 : "r"(a[0]), "r"(a[1]), "r"(a[2]), "r"(a[3]), "r"(b0), "r"(b1));
}

// ============================================================================
// JAX threefry2x32 (partitionable bits path: counter (0,i), xor-fold)
// ============================================================================
__device__ __forceinline__ uint2 threefry2x32_pair(uint32_t k0, uint32_t k1,
                                                   uint32_t x0, uint32_t x1) {
    uint32_t ks2 = k0 ^ k1 ^ 0x1BD11BDAu;
    x0 += k0; x1 += k1;
#define TF_R(r) { x0 += x1; x1 = (x1 << (r)) | (x1 >> (32 - (r))); x1 ^= x0; }
    TF_R(13) TF_R(15) TF_R(26) TF_R(6)
    x0 += k1;  x1 += ks2 + 1u;
    TF_R(17) TF_R(29) TF_R(16) TF_R(24)
    x0 += ks2; x1 += k0 + 2u;
    TF_R(13) TF_R(15) TF_R(26) TF_R(6)
    x0 += k0;  x1 += k1 + 3u;
    TF_R(17) TF_R(29) TF_R(16) TF_R(24)
    x0 += k1;  x1 += ks2 + 4u;
    TF_R(13) TF_R(15) TF_R(26) TF_R(6)
    x0 += ks2; x1 += k0 + 5u;
#undef TF_R
    return make_uint2(x0, x1);
}

__device__ __forceinline__ uint32_t threefry_fold(uint32_t k0, uint32_t k1, uint32_t idx) {
    uint2 o = threefry2x32_pair(k0, k1, 0u, idx);
    return o.x ^ o.y;
}

__global__ void subkey_kernel() {
    if (threadIdx.x == 0) {
        uint2 a = threefry2x32_pair(0u, 42u, 0u, 0u);
        uint2 b = threefry2x32_pair(0u, 42u, 0u, 1u);
        g_subkeys = make_uint4(a.x, a.y, b.x, b.y);
    }
}

// ============================================================================
// Weight quant (both weights, one launch)
// ============================================================================
__global__ __launch_bounds__(256) void quant_w_kernel(const float* __restrict__ W1,
                                                      const float* __restrict__ W2) {
    const int n4w = (HDIM * HDIM) / 4;
    int i = blockIdx.x * blockDim.x + threadIdx.x;
    const float* x = (i < n4w) ? W1 : W2;
    int8_t* q      = (i < n4w) ? g_qw[0] : g_qw[1];
    int j = (i < n4w) ? i : i - n4w;
    float4 v = reinterpret_cast<const float4*>(x)[j];
    int a0 = __float2int_rn(fminf(fmaxf(v.x, -2.5f), 2.5f) * QINV);
    int a1 = __float2int_rn(fminf(fmaxf(v.y, -2.5f), 2.5f) * QINV);
    int a2 = __float2int_rn(fminf(fmaxf(v.z, -2.5f), 2.5f) * QINV);
    int a3 = __float2int_rn(fminf(fmaxf(v.w, -2.5f), 2.5f) * QINV);
    uint32_t pk = (uint32_t)(a0 & 0xff) | ((uint32_t)(a1 & 0xff) << 8)
                | ((uint32_t)(a2 & 0xff) << 16) | ((uint32_t)(a3 & 0xff) << 24);
    reinterpret_cast<uint32_t*>(q)[j] = pk;
}

// ============================================================================
// Activation quant + half of the GEMM1 dropout bitmask
// 8 elements per thread; threads [0, NELT/16) also emit one mask byte.
// ============================================================================
__global__ __launch_bounds__(256) void quant_act_kernel(const float* __restrict__ x,
                                                        int which) {
    int8_t* q = g_qx[which];
    const uint32_t t = blockIdx.x * blockDim.x + threadIdx.x;   // [0, NELT/8)
    const uint32_t e = t * 8u;

    float4 v0 = reinterpret_cast<const float4*>(x + e)[0];
    float4 v1 = reinterpret_cast<const float4*>(x + e)[1];
    int a0 = __float2int_rn(fminf(fmaxf(v0.x, -2.5f), 2.5f) * QINV);
    int a1 = __float2int_rn(fminf(fmaxf(v0.y, -2.5f), 2.5f) * QINV);
    int a2 = __float2int_rn(fminf(fmaxf(v0.z, -2.5f), 2.5f) * QINV);
    int a3 = __float2int_rn(fminf(fmaxf(v0.w, -2.5f), 2.5f) * QINV);
    int a4 = __float2int_rn(fminf(fmaxf(v1.x, -2.5f), 2.5f) * QINV);
    int a5 = __float2int_rn(fminf(fmaxf(v1.y, -2.5f), 2.5f) * QINV);
    int a6 = __float2int_rn(fminf(fmaxf(v1.z, -2.5f), 2.5f) * QINV);
    int a7 = __float2int_rn(fminf(fmaxf(v1.w, -2.5f), 2.5f) * QINV);
    uint2 pk;
    pk.x = (uint32_t)(a0 & 0xff) | ((uint32_t)(a1 & 0xff) << 8)
         | ((uint32_t)(a2 & 0xff) << 16) | ((uint32_t)(a3 & 0xff) << 24);
    pk.y = (uint32_t)(a4 & 0xff) | ((uint32_t)(a5 & 0xff) << 8)
         | ((uint32_t)(a6 & 0xff) << 16) | ((uint32_t)(a7 & 0xff) << 24);
    reinterpret_cast<uint2*>(q + e)[0] = pk;

    // GEMM1 mask bytes: kernel 'which' covers byte range [which*NELT/16, ...)
    if (t < (NELT / 16)) {
        const uint32_t b = t + (uint32_t)which * (NELT / 16);
        const uint32_t i0 = b * 8u;
        const uint4 sk = g_subkeys;
        uint32_t m = 0;
#pragma unroll
        for (int j = 0; j < 8; j++) {
            uint32_t bits = threefry_fold(sk.x, sk.y, i0 + (uint32_t)j);
            m |= (uint32_t)((bits >> 9) < KEEP_THR) << j;
        }
        g_mask[b] = (uint8_t)m;
    }
}

// ============================================================================
// Int8 GEMM (mma.sync m16n8k32): CTA 128x128, K-chunk 128, 3-stage cp.async.
// Epilogue: scale2*acc + bias; gemm0 applies precomputed dropout bitmask,
// gemm1 stores raw (dropout applied later in epi).
// ============================================================================
#define KCHUNKS 8
#define STAGE_BYTES 32768
#define NSTAGES 3

__device__ __forceinline__ void load_stage(const int8_t* __restrict__ X,
                                           const int8_t* __restrict__ Wt,
                                           int m0, int n0, uint32_t smem_base,
                                           int tid, int kc, int slot) {
    uint32_t sb = smem_base + (uint32_t)slot * STAGE_BYTES;
    const int kof = kc * 128;
#pragma unroll
    for (int i = 0; i < 4; i++) {
        int lin = tid + i * 256;
        int row = lin >> 3, seg = lin & 7;
        uint32_t off = SWZ128((uint32_t)(row * 128 + seg * 16));
        cp_async16(sb + off,          X  + (size_t)(m0 + row) * HDIM + kof + seg * 16);
        cp_async16(sb + 16384u + off, Wt + (size_t)(n0 + row) * HDIM + kof + seg * 16);
    }
    CP_COMMIT();
}

__global__ __launch_bounds__(256, 2) void gemm_kernel(const float* __restrict__ bias1,
                                                      const float* __restrict__ bias2) {
    extern __shared__ __align__(1024) char smem[];
    const uint32_t smem_base = smem_u32(smem);
    const int tid  = threadIdx.x;
    const int wid  = tid >> 5, lane = tid & 31;
    const int gemm = blockIdx.y;
    const int m0 = (blockIdx.x >> 3) * 128;
    const int n0 = (blockIdx.x & 7) * 128;
    const int wm = (wid & 3) * 32, wn = (wid >> 2) * 64;

    const int8_t* __restrict__ X  = g_qx[gemm];
    const int8_t* __restrict__ Wt = g_qw[gemm];
    const float*  __restrict__ bias = gemm ? bias2 : bias1;

    uint32_t sA[2], sB[4];
#pragma unroll
    for (int mi = 0; mi < 2; mi++) {
        int row = wm + mi * 16 + ((lane >> 3) & 1) * 8 + (lane & 7);
        sA[mi] = SWZ128((uint32_t)(row * 128 + ((lane >> 4) << 4)));
    }
#pragma unroll
    for (int g = 0; g < 4; g++) {
        int col = wn + g * 16 + ((lane >> 4) << 3) + (lane & 7);
        sB[g] = SWZ128((uint32_t)(col * 128 + (((lane >> 3) & 1) << 4)));
    }

    int acc[2][8][4];
#pragma unroll
    for (int mi = 0; mi < 2; mi++)
#pragma unroll
        for (int nf = 0; nf < 8; nf++)
#pragma unroll
            for (int j = 0; j < 4; j++) acc[mi][nf][j] = 0;

    load_stage(X, Wt, m0, n0, smem_base, tid, 0, 0);
    load_stage(X, Wt, m0, n0, smem_base, tid, 1, 1);

#pragma unroll 1
    for (int kc = 0; kc < KCHUNKS; kc++) {
        if (kc == KCHUNKS - 1) { CP_WAIT(0); } else { CP_WAIT(1); }
        __syncthreads();
        if (kc + 2 < KCHUNKS)
            load_stage(X, Wt, m0, n0, smem_base, tid, kc + 2, (kc + 2) % NSTAGES);

        const uint32_t aBase = smem_base + (uint32_t)(kc % NSTAGES) * STAGE_BYTES;
        const uint32_t bBase = aBase + 16384u;
#pragma unroll
        for (int ks = 0; ks < 4; ks++) {
            uint32_t a[2][4], b[4][4];
            const uint32_t kx = (uint32_t)(ks << 5);
            ldsm4(a[0], aBase + (sA[0] ^ kx));
            ldsm4(a[1], aBase + (sA[1] ^ kx));
#pragma unroll
            for (int g = 0; g < 4; g++) ldsm4(b[g], bBase + (sB[g] ^ kx));
#pragma unroll
            for (int mi = 0; mi < 2; mi++)
#pragma unroll
                for (int nf = 0; nf < 8; nf++)
                    imma16832(acc[mi][nf], a[mi],
                              b[nf >> 1][(nf & 1) * 2], b[nf >> 1][(nf & 1) * 2 + 1]);
        }
        // no trailing __syncthreads: with 3 stages the slot written next
        // iteration was last read before the barrier every warp passed.
    }

    // ---- epilogue ----
    const float scale2 = QSCALE * QSCALE;
    const float inv_keep = 1.0f / 0.9f;
    float* __restrict__ Y = g_y[gemm];

    if (gemm == 0) {
#pragma unroll
        for (int nf = 0; nf < 8; nf++) {
            const int c = n0 + wn + nf * 8 + 2 * (lane & 3);
            const float2 bv = *reinterpret_cast<const float2*>(bias + c);
#pragma unroll
            for (int mi = 0; mi < 2; mi++) {
#pragma unroll
                for (int h = 0; h < 2; h++) {
                    const int r = m0 + wm + mi * 16 + (lane >> 2) + h * 8;
                    float v0 = (float)acc[mi][nf][h * 2 + 0] * scale2 + bv.x;
                    float v1 = (float)acc[mi][nf][h * 2 + 1] * scale2 + bv.y;
                    const uint32_t idx = (uint32_t)r * HDIM + (uint32_t)c;
                    const uint32_t mb = g_mask[idx >> 3];
                    v0 = ((mb >> (c & 7)) & 1u) ? v0 * inv_keep : 0.0f;
                    v1 = ((mb >> ((c & 7) + 1)) & 1u) ? v1 * inv_keep : 0.0f;
                    *reinterpret_cast<float2*>(Y + (size_t)r * HDIM + c) = make_float2(v0, v1);
                }
            }
        }
    } else {
#pragma unroll
        for (int nf = 0; nf < 8; nf++) {
            const int c = n0 + wn + nf * 8 + 2 * (lane & 3);
            const float2 bv = *reinterpret_cast<const float2*>(bias + c);
#pragma unroll
            for (int mi = 0; mi < 2; mi++) {
#pragma unroll
                for (int h = 0; h < 2; h++) {
                    const int r = m0 + wm + mi * 16 + (lane >> 2) + h * 8;
                    float v0 = (float)acc[mi][nf][h * 2 + 0] * scale2 + bv.x;
                    float v1 = (float)acc[mi][nf][h * 2 + 1] * scale2 + bv.y;
                    *reinterpret_cast<float2*>(Y + (size_t)r * HDIM + c) = make_float2(v0, v1);
                }
            }
        }
    }
}

// ============================================================================
// Residual + dropout(gemm2, inline threefry) + 2x LayerNorm
// ============================================================================
__device__ __forceinline__ float blk_sum(float v, float* sbuf) {
    const int lane = threadIdx.x & 31, w = threadIdx.x >> 5;
#pragma unroll
    for (int o = 16; o; o >>= 1) v += __shfl_xor_sync(0xffffffffu, v, o);
    __syncthreads();
    if (lane == 0) sbuf[w] = v;
    __syncthreads();
    float t = 0.f;
#pragma unroll
    for (int i = 0; i < 8; i++) t += sbuf[i];
    return t;
}

__global__ __launch_bounds__(256) void epi_kernel(
    const float* __restrict__ inp,
    const float* __restrict__ g1, const float* __restrict__ be1,
    const float* __restrict__ g2, const float* __restrict__ be2,
    float* __restrict__ out)
{
    __shared__ float sbuf[8];
    const int row = blockIdx.x;
    const int tid = threadIdx.x;
    const size_t base = (size_t)row * HDIM;
    const int o = tid * 4;
    const float inv_keep = 1.0f / 0.9f;

    const float4 xin = *reinterpret_cast<const float4*>(inp + base + o);
    const uint4 sk = g_subkeys;

#pragma unroll 1
    for (int p = 0; p < 2; p++) {
        const float* __restrict__ gg = p ? g2  : g1;
        const float* __restrict__ ee = p ? be2 : be1;
        const float4 y = *reinterpret_cast<const float4*>(g_y[p] + base + o);
        float v[4] = { y.x, y.y, y.z, y.w };

        if (p == 1) {
            const uint32_t i0 = (uint32_t)(base + o);
#pragma unroll
            for (int j = 0; j < 4; j++) {
                uint32_t bits = threefry_fold(sk.z, sk.w, i0 + (uint32_t)j);
                v[j] = ((bits >> 9) < KEEP_THR) ? v[j] * inv_keep : 0.0f;
            }
        }
        float v0 = v[0] + xin.x, v1 = v[1] + xin.y, v2 = v[2] + xin.z, v3 = v[3] + xin.w;

        float s  = blk_sum(v0 + v1 + v2 + v3, sbuf);
        float mu = s * (1.0f / 1024.0f);
        float d0 = v0 - mu, d1 = v1 - mu, d2 = v2 - mu, d3 = v3 - mu;
        float sq  = blk_sum(d0 * d0 + d1 * d1 + d2 * d2 + d3 * d3, sbuf);
        float rs  = rsqrtf(sq * (1.0f / 1024.0f) + 1e-12f);

        const float4 gv = *reinterpret_cast<const float4*>(gg + o);
        const float4 ev = *reinterpret_cast<const float4*>(ee + o);
        float4 ov = make_float4(d0 * rs * gv.x + ev.x, d1 * rs * gv.y + ev.y,
                                d2 * rs * gv.z + ev.z, d3 * rs * gv.w + ev.w);
        *reinterpret_cast<float4*>(out + (size_t)p * NELT + base + o) = ov;
    }
}

// ============================================================================
// Launch: subkey(0), quant_w(1), quant_act hs1(2), quant_act hs2(3),
//         gemm(4)  <-- ncu capture slot, epi(5)
// ============================================================================
extern "C" void kernel_launch(void* const* d_in, const int* in_sizes, int n_in,
                              void* d_out, int out_size) {
    const float* hs1 = (const float*)d_in[0];
    const float* hs2 = (const float*)d_in[1];
    const float* inp = (const float*)d_in[2];
    const float* W1  = (const float*)d_in[3];
    const float* b1  = (const float*)d_in[4];
    const float* W2  = (const float*)d_in[5];
    const float* b2  = (const float*)d_in[6];
    const float* g1  = (const float*)d_in[7];
    const float* be1 = (const float*)d_in[8];
    const float* g2  = (const float*)d_in[9];
    const float* be2 = (const float*)d_in[10];
    float* out = (float*)d_out;

    subkey_kernel<<<1, 32>>>();
    quant_w_kernel<<<(2 * (HDIM * HDIM) / 4) / 256, 256>>>(W1, W2);
    quant_act_kernel<<<(NELT / 8) / 256, 256>>>(hs1, 0);
    quant_act_kernel<<<(NELT / 8) / 256, 256>>>(hs2, 1);

    cudaFuncSetAttribute(gemm_kernel, cudaFuncAttributeMaxDynamicSharedMemorySize,
                         NSTAGES * STAGE_BYTES);
    gemm_kernel<<<dim3(1024, 2), 256, NSTAGES * STAGE_BYTES>>>(b1, b2);

    epi_kernel<<<BS_ROWS, 256>>>(inp, g1, be1, g2, be2, out);
}